// round 15
// baseline (speedup 1.0000x reference)
#include <cuda_runtime.h>

// Problem constants (fixed by the reference): B=8, C=64, H=W=256.
#define Bn   8
#define Cn   64
#define Hn   256
#define Wn   256
#define HWn  (Hn * Wn)          // 65536
#define FULLM 0xFFFFFFFFu
#define TPB  128                // 4 warps: doubles resident blocks per SM
                                // (more independent latency chains in flight)

__global__ __launch_bounds__(TPB)
void warp_bilinear_kernel(const float* __restrict__ phi,
                          const float* __restrict__ x_enc,
                          const float* __restrict__ m,
                          float* __restrict__ out)
{
    __shared__ float wgt_s[4][32];      // [corner][rank]
    __shared__ int   off_s[4][32];      // [corner][rank]
    __shared__ int   rank_s[32];        // pixel lane -> rank, -1 if invalid
    __shared__ int   nval_s;
    __shared__ float res_s[32 * 65];    // [rank][channel], pad 65 (bank-safe)

    const int tid   = threadIdx.x;
    const int lane  = tid & 31;
    const int wslot = tid >> 5;

    const int pixwarp = blockIdx.x;          // 0..16383: 32-pixel group
    const int b       = pixwarp >> 11;       // 2048 groups per batch image
    const int hwg     = (pixwarp & 2047) << 5;

    // ---- Phase 1: warp 0 computes sampling setup ONCE for the 32 pixels ----
    if (wslot == 0) {
        const int hw = hwg + lane;
        const int h  = hw >> 8;
        const int w  = hw & (Wn - 1);

        const float px = phi[(b * 2 + 0) * HWn + hw];
        const float py = phi[(b * 2 + 1) * HWn + hw];
        const float mv = m[b * HWn + hw];

        // vgrid = 2*(coord+phi)/(dim-1) - 1 + 2*phi ; unnormalize (align_corners=False)
        const float vx = 2.0f * ((float)w + px) / (float)(Wn - 1) - 1.0f + 2.0f * px;
        const float vy = 2.0f * ((float)h + py) / (float)(Hn - 1) - 1.0f + 2.0f * py;
        const float ix = (vx + 1.0f) * (0.5f * (float)Wn) - 0.5f;
        const float iy = (vy + 1.0f) * (0.5f * (float)Hn) - 0.5f;

        const float x0f = floorf(ix);
        const float y0f = floorf(iy);
        const int   x0  = (int)x0f;
        const int   y0  = (int)y0f;
        const int   x1  = x0 + 1;
        const int   y1  = y0 + 1;

        const float wx1 = ix - x0f;
        const float wx0 = 1.0f - wx1;
        const float wy1 = iy - y0f;
        const float wy0 = 1.0f - wy1;

        const float vx0 = (x0 >= 0 && x0 < Wn) ? 1.0f : 0.0f;
        const float vx1 = (x1 >= 0 && x1 < Wn) ? 1.0f : 0.0f;
        const float vy0 = (y0 >= 0 && y0 < Hn) ? 1.0f : 0.0f;
        const float vy1 = (y1 >= 0 && y1 < Hn) ? 1.0f : 0.0f;

        // Fold validity AND mask into corner weights (zeros padding, out *= m)
        const float w00 = wy0 * wx0 * vy0 * vx0 * mv;
        const float w01 = wy0 * wx1 * vy0 * vx1 * mv;
        const float w10 = wy1 * wx0 * vy1 * vx0 * mv;
        const float w11 = wy1 * wx1 * vy1 * vx1 * mv;

        const int x0c = min(max(x0, 0), Wn - 1);
        const int x1c = min(max(x1, 0), Wn - 1);
        const int y0c = min(max(y0, 0), Hn - 1);
        const int y1c = min(max(y1, 0), Hn - 1);

        const bool pvalid = (w00 != 0.0f) | (w01 != 0.0f) |
                            (w10 != 0.0f) | (w11 != 0.0f);
        const unsigned blt = __ballot_sync(FULLM, pvalid);
        const int rank = __popc(blt & ((1u << lane) - 1u));

        rank_s[lane] = pvalid ? rank : -1;
        if (pvalid) {
            wgt_s[0][rank] = w00;  off_s[0][rank] = y0c * Wn + x0c;
            wgt_s[1][rank] = w01;  off_s[1][rank] = y0c * Wn + x1c;
            wgt_s[2][rank] = w10;  off_s[2][rank] = y1c * Wn + x0c;
            wgt_s[3][rank] = w11;  off_s[3][rank] = y1c * Wn + x1c;
        }
        if (lane == 0) nval_s = __popc(blt);
    }
    __syncthreads();

    const int k     = nval_s;
    const int baseB = b * Cn * HWn;

    // ---- Phase 2: block-wide gather, task = (valid pixel rank, channel) ----
    if (k > 0) {
        const int ntask = k << 6;                 // k * 64 channels
        for (int t = tid; t < ntask; t += TPB) {
            const int j  = t >> 6;                // rank
            const int ch = t & 63;
            const float W00 = wgt_s[0][j];
            const float W01 = wgt_s[1][j];
            const float W10 = wgt_s[2][j];
            const float W11 = wgt_s[3][j];
            const int   O00 = off_s[0][j];
            const int   O01 = off_s[1][j];
            const int   O10 = off_s[2][j];
            const int   O11 = off_s[3][j];
            const float* __restrict__ pc = x_enc + baseB + ch * HWn;
            float a = 0.0f, bv = 0.0f, cv = 0.0f, dv = 0.0f;
            if (W00 != 0.0f) a  = __ldg(pc + O00);
            if (W01 != 0.0f) bv = __ldg(pc + O01);
            if (W10 != 0.0f) cv = __ldg(pc + O10);
            if (W11 != 0.0f) dv = __ldg(pc + O11);
            res_s[j * 65 + ch] =
                fmaf(W00, a, fmaf(W01, bv, fmaf(W10, cv, W11 * dv)));
        }
        __syncthreads();
    }

    // ---- Phase 3: vectorized stores. Thread t owns pixel quad 4*(t&7);
    // 4 rounds of STG.128 cover 64ch x 32px with full-warp 128B lines. ----
    const int q  = (tid & 7) << 2;                // pixel base within group
    const int r0 = rank_s[q + 0];
    const int r1 = rank_s[q + 1];
    const int r2 = rank_s[q + 2];
    const int r3 = rank_s[q + 3];

#pragma unroll
    for (int rd = 0; rd < 4; ++rd) {
        const int ch = (tid >> 3) + (rd << 4);    // 0..63
        float4 v;
        v.x = (r0 >= 0) ? res_s[r0 * 65 + ch] : 0.0f;
        v.y = (r1 >= 0) ? res_s[r1 * 65 + ch] : 0.0f;
        v.z = (r2 >= 0) ? res_s[r2 * 65 + ch] : 0.0f;
        v.w = (r3 >= 0) ? res_s[r3 * 65 + ch] : 0.0f;
        __stcs((float4*)(out + baseB + ch * HWn + hwg + q), v);
    }
}

extern "C" void kernel_launch(void* const* d_in, const int* in_sizes, int n_in,
                              void* d_out, int out_size)
{
    const float* phi   = (const float*)d_in[0];
    const float* x_enc = (const float*)d_in[1];
    const float* m     = (const float*)d_in[2];
    float* out         = (float*)d_out;

    const int blocks = (Bn * HWn) / 32;    // 16384 pixel-groups
    warp_bilinear_kernel<<<blocks, TPB>>>(phi, x_enc, m, out);
}

// round 16
// speedup vs baseline: 1.0497x; 1.0497x over previous
#include <cuda_runtime.h>

// Problem constants (fixed by the reference): B=8, C=64, H=W=256.
#define Bn   8
#define Cn   64
#define Hn   256
#define Wn   256
#define HWn  (Hn * Wn)          // 65536
#define FULLM 0xFFFFFFFFu
#define TPB  256                // 8 warps: block = 32 pixels x 64 channels

__global__ __launch_bounds__(TPB)
void warp_bilinear_kernel(const float* __restrict__ phi,
                          const float* __restrict__ x_enc,
                          const float* __restrict__ m,
                          float* __restrict__ out)
{
    __shared__ float wgt_s[4][32];      // [corner][rank]
    __shared__ int   off_s[4][32];      // [corner][rank]
    __shared__ int   rank_s[32];        // pixel lane -> rank, -1 if invalid
    __shared__ int   nval_s;
    __shared__ float res_s[32 * 65];    // [rank][channel], pad 65 (bank-safe)

    const int tid   = threadIdx.x;
    const int lane  = tid & 31;
    const int wslot = tid >> 5;

    const int pixwarp = blockIdx.x;          // 0..16383: 32-pixel group
    const int b       = pixwarp >> 11;       // 2048 groups per batch image
    const int hwg     = (pixwarp & 2047) << 5;

    // ---- Phase 1: warp 0 computes sampling setup ONCE for the 32 pixels ----
    if (wslot == 0) {
        const int hw = hwg + lane;
        const int h  = hw >> 8;
        const int w  = hw & (Wn - 1);

        const float px = phi[(b * 2 + 0) * HWn + hw];
        const float py = phi[(b * 2 + 1) * HWn + hw];
        const float mv = m[b * HWn + hw];

        // vgrid = 2*(coord+phi)/(dim-1) - 1 + 2*phi ; unnormalize (align_corners=False)
        const float vx = 2.0f * ((float)w + px) / (float)(Wn - 1) - 1.0f + 2.0f * px;
        const float vy = 2.0f * ((float)h + py) / (float)(Hn - 1) - 1.0f + 2.0f * py;
        const float ix = (vx + 1.0f) * (0.5f * (float)Wn) - 0.5f;
        const float iy = (vy + 1.0f) * (0.5f * (float)Hn) - 0.5f;

        const float x0f = floorf(ix);
        const float y0f = floorf(iy);
        const int   x0  = (int)x0f;
        const int   y0  = (int)y0f;
        const int   x1  = x0 + 1;
        const int   y1  = y0 + 1;

        const float wx1 = ix - x0f;
        const float wx0 = 1.0f - wx1;
        const float wy1 = iy - y0f;
        const float wy0 = 1.0f - wy1;

        const float vx0 = (x0 >= 0 && x0 < Wn) ? 1.0f : 0.0f;
        const float vx1 = (x1 >= 0 && x1 < Wn) ? 1.0f : 0.0f;
        const float vy0 = (y0 >= 0 && y0 < Hn) ? 1.0f : 0.0f;
        const float vy1 = (y1 >= 0 && y1 < Hn) ? 1.0f : 0.0f;

        // Fold validity AND mask into corner weights (zeros padding, out *= m)
        const float w00 = wy0 * wx0 * vy0 * vx0 * mv;
        const float w01 = wy0 * wx1 * vy0 * vx1 * mv;
        const float w10 = wy1 * wx0 * vy1 * vx0 * mv;
        const float w11 = wy1 * wx1 * vy1 * vx1 * mv;

        const int x0c = min(max(x0, 0), Wn - 1);
        const int x1c = min(max(x1, 0), Wn - 1);
        const int y0c = min(max(y0, 0), Hn - 1);
        const int y1c = min(max(y1, 0), Hn - 1);

        const bool pvalid = (w00 != 0.0f) | (w01 != 0.0f) |
                            (w10 != 0.0f) | (w11 != 0.0f);
        const unsigned blt = __ballot_sync(FULLM, pvalid);
        const int rank = __popc(blt & ((1u << lane) - 1u));

        rank_s[lane] = pvalid ? rank : -1;
        if (pvalid) {
            wgt_s[0][rank] = w00;  off_s[0][rank] = y0c * Wn + x0c;
            wgt_s[1][rank] = w01;  off_s[1][rank] = y0c * Wn + x1c;
            wgt_s[2][rank] = w10;  off_s[2][rank] = y1c * Wn + x0c;
            wgt_s[3][rank] = w11;  off_s[3][rank] = y1c * Wn + x1c;
        }
        if (lane == 0) nval_s = __popc(blt);
    }
    __syncthreads();

    const int k     = nval_s;
    const int baseB = b * Cn * HWn;

    // ---- Phase 2: block-wide gather, task = (valid pixel rank, channel) ----
    if (k > 0) {
        const int ntask = k << 6;                 // k * 64 channels
        for (int t = tid; t < ntask; t += TPB) {
            const int j  = t >> 6;                // rank
            const int ch = t & 63;
            const float W00 = wgt_s[0][j];
            const float W01 = wgt_s[1][j];
            const float W10 = wgt_s[2][j];
            const float W11 = wgt_s[3][j];
            const int   O00 = off_s[0][j];
            const int   O01 = off_s[1][j];
            const int   O10 = off_s[2][j];
            const int   O11 = off_s[3][j];
            const float* __restrict__ pc = x_enc + baseB + ch * HWn;
            float a = 0.0f, bv = 0.0f, cv = 0.0f, dv = 0.0f;
            if (W00 != 0.0f) a  = __ldg(pc + O00);
            if (W01 != 0.0f) bv = __ldg(pc + O01);
            if (W10 != 0.0f) cv = __ldg(pc + O10);
            if (W11 != 0.0f) dv = __ldg(pc + O11);
            res_s[j * 65 + ch] =
                fmaf(W00, a, fmaf(W01, bv, fmaf(W10, cv, W11 * dv)));
        }
        __syncthreads();
    }

    // ---- Phase 3: vectorized stores. Thread t owns (channel = t>>3,
    // pixel quad = 4*(t&7)); 2 rounds of STG.128 cover 64ch x 32px. ----
    const int q  = (tid & 7) << 2;                // pixel base within group
    const int r0 = rank_s[q + 0];
    const int r1 = rank_s[q + 1];
    const int r2 = rank_s[q + 2];
    const int r3 = rank_s[q + 3];

#pragma unroll
    for (int rd = 0; rd < 2; ++rd) {
        const int ch = (tid >> 3) + (rd << 5);    // 0..63
        float4 v;
        v.x = (r0 >= 0) ? res_s[r0 * 65 + ch] : 0.0f;
        v.y = (r1 >= 0) ? res_s[r1 * 65 + ch] : 0.0f;
        v.z = (r2 >= 0) ? res_s[r2 * 65 + ch] : 0.0f;
        v.w = (r3 >= 0) ? res_s[r3 * 65 + ch] : 0.0f;
        __stcs((float4*)(out + baseB + ch * HWn + hwg + q), v);
    }
}

extern "C" void kernel_launch(void* const* d_in, const int* in_sizes, int n_in,
                              void* d_out, int out_size)
{
    const float* phi   = (const float*)d_in[0];
    const float* x_enc = (const float*)d_in[1];
    const float* m     = (const float*)d_in[2];
    float* out         = (float*)d_out;

    const int blocks = (Bn * HWn) / 32;    // 16384 pixel-groups
    warp_bilinear_kernel<<<blocks, TPB>>>(phi, x_enc, m, out);
}

// round 17
// speedup vs baseline: 1.0792x; 1.0281x over previous
#include <cuda_runtime.h>

// Problem constants (fixed by the reference): B=8, C=64, H=W=256.
#define Bn   8
#define Cn   64
#define Hn   256
#define Wn   256
#define HWn  (Hn * Wn)          // 65536
#define FULLM 0xFFFFFFFFu
#define TPB  256                // block = 64 pixels x 64 channels
#define PIX  64                 // pixels per block (2 setup warps)

__global__ __launch_bounds__(TPB)
void warp_bilinear_kernel(const float* __restrict__ phi,
                          const float* __restrict__ x_enc,
                          const float* __restrict__ m,
                          float* __restrict__ out)
{
    __shared__ float wgt_s[4][PIX];     // [corner][half*32+rank]
    __shared__ int   off_s[4][PIX];
    __shared__ int   rank_s[PIX];       // pixel -> half*32+rank, -1 if invalid
    __shared__ int   nval_s[2];         // valid count per half
    __shared__ float res_s[PIX * 65];   // [half*32+rank][channel], pad 65

    const int tid   = threadIdx.x;
    const int lane  = tid & 31;
    const int wslot = tid >> 5;

    const int grp = blockIdx.x;              // 0..8191: 64-pixel group
    const int b   = grp >> 10;               // 1024 groups per batch image
    const int hwg = (grp & 1023) << 6;       // base hw of the 64 pixels

    // ---- Phase 1: warps 0 and 1 compute setup for their 32-pixel half ----
    if (wslot < 2) {
        const int hw = hwg + wslot * 32 + lane;
        const int h  = hw >> 8;
        const int w  = hw & (Wn - 1);

        const float px = phi[(b * 2 + 0) * HWn + hw];
        const float py = phi[(b * 2 + 1) * HWn + hw];
        const float mv = m[b * HWn + hw];

        // vgrid = 2*(coord+phi)/(dim-1) - 1 + 2*phi ; unnormalize (align_corners=False)
        const float vx = 2.0f * ((float)w + px) / (float)(Wn - 1) - 1.0f + 2.0f * px;
        const float vy = 2.0f * ((float)h + py) / (float)(Hn - 1) - 1.0f + 2.0f * py;
        const float ix = (vx + 1.0f) * (0.5f * (float)Wn) - 0.5f;
        const float iy = (vy + 1.0f) * (0.5f * (float)Hn) - 0.5f;

        const float x0f = floorf(ix);
        const float y0f = floorf(iy);
        const int   x0  = (int)x0f;
        const int   y0  = (int)y0f;
        const int   x1  = x0 + 1;
        const int   y1  = y0 + 1;

        const float wx1 = ix - x0f;
        const float wx0 = 1.0f - wx1;
        const float wy1 = iy - y0f;
        const float wy0 = 1.0f - wy1;

        const float vx0 = (x0 >= 0 && x0 < Wn) ? 1.0f : 0.0f;
        const float vx1 = (x1 >= 0 && x1 < Wn) ? 1.0f : 0.0f;
        const float vy0 = (y0 >= 0 && y0 < Hn) ? 1.0f : 0.0f;
        const float vy1 = (y1 >= 0 && y1 < Hn) ? 1.0f : 0.0f;

        // Fold validity AND mask into corner weights (zeros padding, out *= m)
        const float w00 = wy0 * wx0 * vy0 * vx0 * mv;
        const float w01 = wy0 * wx1 * vy0 * vx1 * mv;
        const float w10 = wy1 * wx0 * vy1 * vx0 * mv;
        const float w11 = wy1 * wx1 * vy1 * vx1 * mv;

        const int x0c = min(max(x0, 0), Wn - 1);
        const int x1c = min(max(x1, 0), Wn - 1);
        const int y0c = min(max(y0, 0), Hn - 1);
        const int y1c = min(max(y1, 0), Hn - 1);

        const bool pvalid = (w00 != 0.0f) | (w01 != 0.0f) |
                            (w10 != 0.0f) | (w11 != 0.0f);
        const unsigned blt = __ballot_sync(FULLM, pvalid);
        const int rank = __popc(blt & ((1u << lane) - 1u));
        const int slot = wslot * 32 + rank;       // compacted slot (per half)

        rank_s[wslot * 32 + lane] = pvalid ? slot : -1;
        if (pvalid) {
            wgt_s[0][slot] = w00;  off_s[0][slot] = y0c * Wn + x0c;
            wgt_s[1][slot] = w01;  off_s[1][slot] = y0c * Wn + x1c;
            wgt_s[2][slot] = w10;  off_s[2][slot] = y1c * Wn + x0c;
            wgt_s[3][slot] = w11;  off_s[3][slot] = y1c * Wn + x1c;
        }
        if (lane == 0) nval_s[wslot] = __popc(blt);
    }
    __syncthreads();

    const int k0    = nval_s[0];
    const int k1    = nval_s[1];
    const int baseB = b * Cn * HWn;

    // ---- Phase 2: block-wide gather; tasks = (k0+k1) * 64 channels ----
    if ((k0 | k1) > 0) {
        const int n0    = k0 << 6;
        const int ntask = (k0 + k1) << 6;
        for (int t = tid; t < ntask; t += TPB) {
            // Map task to compacted slot: first n0 tasks -> half 0, rest -> half 1.
            const int tt   = (t < n0) ? t : (t - n0);
            const int base = (t < n0) ? 0 : 32;
            const int j    = base + (tt >> 6);    // slot
            const int ch   = tt & 63;
            const float W00 = wgt_s[0][j];
            const float W01 = wgt_s[1][j];
            const float W10 = wgt_s[2][j];
            const float W11 = wgt_s[3][j];
            const int   O00 = off_s[0][j];
            const int   O01 = off_s[1][j];
            const int   O10 = off_s[2][j];
            const int   O11 = off_s[3][j];
            const float* __restrict__ pc = x_enc + baseB + ch * HWn;
            float a = 0.0f, bv = 0.0f, cv = 0.0f, dv = 0.0f;
            if (W00 != 0.0f) a  = __ldg(pc + O00);
            if (W01 != 0.0f) bv = __ldg(pc + O01);
            if (W10 != 0.0f) cv = __ldg(pc + O10);
            if (W11 != 0.0f) dv = __ldg(pc + O11);
            res_s[j * 65 + ch] =
                fmaf(W00, a, fmaf(W01, bv, fmaf(W10, cv, W11 * dv)));
        }
        __syncthreads();
    }

    // ---- Phase 3: vectorized stores. Thread t owns pixel quad 4*(t&15),
    // channel (t>>4) + 16*rd; 4 rounds of STG.128 cover 64ch x 64px. ----
    const int q  = (tid & 15) << 2;               // pixel base within group
    const int r0 = rank_s[q + 0];
    const int r1 = rank_s[q + 1];
    const int r2 = rank_s[q + 2];
    const int r3 = rank_s[q + 3];

#pragma unroll
    for (int rd = 0; rd < 4; ++rd) {
        const int ch = (tid >> 4) + (rd << 4);    // 0..63
        float4 v;
        v.x = (r0 >= 0) ? res_s[r0 * 65 + ch] : 0.0f;
        v.y = (r1 >= 0) ? res_s[r1 * 65 + ch] : 0.0f;
        v.z = (r2 >= 0) ? res_s[r2 * 65 + ch] : 0.0f;
        v.w = (r3 >= 0) ? res_s[r3 * 65 + ch] : 0.0f;
        __stcs((float4*)(out + baseB + ch * HWn + hwg + q), v);
    }
}

extern "C" void kernel_launch(void* const* d_in, const int* in_sizes, int n_in,
                              void* d_out, int out_size)
{
    const float* phi   = (const float*)d_in[0];
    const float* x_enc = (const float*)d_in[1];
    const float* m     = (const float*)d_in[2];
    float* out         = (float*)d_out;

    const int blocks = (Bn * HWn) / PIX;   // 8192 pixel-groups
    warp_bilinear_kernel<<<blocks, TPB>>>(phi, x_enc, m, out);
}